// round 7
// baseline (speedup 1.0000x reference)
#include <cuda_runtime.h>

#define BATCH 128
#define DIM   4096

typedef unsigned long long ull;

// 4MB intermediate scratch (float2 as float4-aligned storage)
__device__ float4 g_inter4[BATCH * DIM / 2];

__device__ __forceinline__ ull pack2(float lo, float hi) {
    ull r;
    asm("mov.b64 %0, {%1, %2};" : "=l"(r) : "f"(lo), "f"(hi));
    return r;
}
__device__ __forceinline__ void unpack2(ull v, float& lo, float& hi) {
    asm("mov.b64 {%0, %1}, %2;" : "=f"(lo), "=f"(hi) : "l"(v));
}
__device__ __forceinline__ ull ffma2(ull a, ull b, ull c) {
    ull d;
    asm("fma.rn.f32x2 %0, %1, %2, %3;" : "=l"(d) : "l"(a), "l"(b), "l"(c));
    return d;
}

// Swap-free complex MAC:
//   accA += (Ur,Ur)*(xr,xi) ; accB += (Ui,Ui)*(xr,xi)
//   yr = accA.lo - accB.hi ; yi = accA.hi + accB.lo
// Gate entry G[kp*16+k] = float4(Ur,Ur,Ui,Ui) with Ur=ar, Ui=-ai.

// 2 fibers x 4 outputs MAC for one kp. Gr = G + kp*16 + q.
__device__ __forceinline__ void mac2(const float4* __restrict__ Gr,
                                     ull xa, ull xb,
                                     ull accA[2][4], ull accB[2][4]) {
    #pragma unroll
    for (int j = 0; j < 4; j++) {
        ulonglong2 g = *reinterpret_cast<const ulonglong2*>(Gr + 4 * j);
        accA[0][j] = ffma2(g.x, xa, accA[0][j]);
        accB[0][j] = ffma2(g.y, xa, accB[0][j]);
        accA[1][j] = ffma2(g.x, xb, accA[1][j]);
        accB[1][j] = ffma2(g.y, xb, accB[1][j]);
    }
}

__device__ __forceinline__ float2 combine(ull a, ull b) {
    float alo, ahi, blo, bhi;
    unpack2(a, alo, ahi);
    unpack2(b, blo, bhi);
    return make_float2(alo - bhi, ahi + blo);
}

// stage V (stride 17) with 128 threads
__device__ __forceinline__ void stage_V(float* Vs, const float* evecs, int t) {
    #pragma unroll
    for (int r = 0; r < 2; r++) {
        int e = t + r * 128;
        Vs[(e >> 4) * 17 + (e & 15)] = evecs[e];
    }
}

// build one gate entry (k,kp) for cs/sn of a single gate
__device__ __forceinline__ float4 gate_entry(const float* Vs, const float* cs,
                                             const float* sn, int k, int kp) {
    float ar = 0.f, ai = 0.f;
    #pragma unroll
    for (int m = 0; m < 16; m++) {
        float p = Vs[k * 17 + m] * Vs[kp * 17 + m];
        ar += p * cs[m];
        ai += p * sn[m];
    }
    return make_float4(ar, ar, -ai, -ai);
}

// ============================================================
// Kernel 1: apply U2 (index c) then U1 (index b) on an a-slice.
// grid = BATCH*4; block = 128.  Slice: a in [4*as, 4*as+4).
// ============================================================
__global__ __launch_bounds__(128)
void k1_steps01(const float* __restrict__ thetas,
                const float* __restrict__ evecs,
                const float* __restrict__ evals,
                const float* __restrict__ sreal,
                const float* __restrict__ simag)
{
    __shared__ float  Vs[272];
    __shared__ float  cs[32], sn[32];        // gates 1 (U1), 2 (U2)
    __shared__ float4 g1s[256], g2s[256];    // G[kp*16+k]
    __shared__ float2 S[1088];               // padded slice state

    const int t = threadIdx.x;
    const int batch = blockIdx.x >> 2;
    const int a0 = (blockIdx.x & 3) * 4;

    stage_V(Vs, evecs, t);
    if (t < 32) {
        int g = 1 + (t >> 4), m = t & 15;
        float s, c;
        sincosf(thetas[g] * evals[m], &s, &c);
        cs[t] = c;
        sn[t] = s;
    }
    __syncthreads();

    #pragma unroll
    for (int r = 0; r < 2; r++) {
        int e = t + r * 128;
        int k = e >> 4, kp = e & 15;
        g1s[kp * 16 + k] = gate_entry(Vs, cs + 0,  sn + 0,  k, kp);
        g2s[kp * 16 + k] = gate_entry(Vs, cs + 16, sn + 16, k, kp);
    }
    __syncthreads();

    const int hh = t >> 2, q = t & 3;        // hh in [0,32)
    const int f0 = 2 * hh;
    const int ia = f0 >> 4;                  // a within slice
    const int b  = f0 & 15;                  // even; fibers (ia,b),(ia,b+1)

    // ---- step A: contract c (contiguous in gmem) with U2 ----
    {
        const float* xr0 = sreal + batch * DIM + (a0 + ia) * 256 + b * 16;
        const float* xi0 = simag + batch * DIM + (a0 + ia) * 256 + b * 16;

        ull accA[2][4], accB[2][4];
        #pragma unroll
        for (int f = 0; f < 2; f++)
            #pragma unroll
            for (int j = 0; j < 4; j++) { accA[f][j] = 0ULL; accB[f][j] = 0ULL; }

        #pragma unroll
        for (int ch = 0; ch < 4; ch++) {
            float4 ra = *reinterpret_cast<const float4*>(xr0 + 4 * ch);
            float4 ja = *reinterpret_cast<const float4*>(xi0 + 4 * ch);
            float4 rb = *reinterpret_cast<const float4*>(xr0 + 16 + 4 * ch);
            float4 jb = *reinterpret_cast<const float4*>(xi0 + 16 + 4 * ch);
            ull xa[4] = { pack2(ra.x, ja.x), pack2(ra.y, ja.y),
                          pack2(ra.z, ja.z), pack2(ra.w, ja.w) };
            ull xb[4] = { pack2(rb.x, jb.x), pack2(rb.y, jb.y),
                          pack2(rb.z, jb.z), pack2(rb.w, jb.w) };
            #pragma unroll
            for (int cc = 0; cc < 4; cc++) {
                int kp = 4 * ch + cc;
                mac2(g2s + kp * 16 + q, xa[cc], xb[cc], accA, accB);
            }
        }
        // store y[ia, b+f, k] to S in [ia][k][b] layout, pad 1/16
        #pragma unroll
        for (int f = 0; f < 2; f++)
            #pragma unroll
            for (int j = 0; j < 4; j++) {
                int k = q + 4 * j;
                int s = ia * 256 + k * 16 + (b + f);
                S[s + (s >> 4)] = combine(accA[f][j], accB[f][j]);
            }
    }
    __syncthreads();

    // ---- step B: contract b with U1; fibers (ia, c), (ia, c+1) ----
    {
        const int c = b;                     // reuse even pairing
        const int base0 = ia * 272 + c * 17;
        const int base1 = base0 + 17;

        ull accA[2][4], accB[2][4];
        #pragma unroll
        for (int f = 0; f < 2; f++)
            #pragma unroll
            for (int j = 0; j < 4; j++) { accA[f][j] = 0ULL; accB[f][j] = 0ULL; }

        #pragma unroll
        for (int kp = 0; kp < 16; kp++) {
            float2 x0 = S[base0 + kp];
            float2 x1 = S[base1 + kp];
            mac2(g1s + kp * 16 + q, pack2(x0.x, x0.y), pack2(x1.x, x1.y),
                 accA, accB);
        }
        // write z[a'=a0+ia, b=k, c+f] to inter[batch][bc][a']
        float2* inter = reinterpret_cast<float2*>(g_inter4) + batch * DIM;
        #pragma unroll
        for (int f = 0; f < 2; f++)
            #pragma unroll
            for (int j = 0; j < 4; j++) {
                int k = q + 4 * j;
                inter[k * 256 + (c + f) * 16 + a0 + ia] =
                    combine(accA[f][j], accB[f][j]);
            }
    }
}

// ============================================================
// Kernel 2: contract a' with U0; fibers contiguous in inter.
// grid = BATCH*4; block = 128.  Slice: bc in [64*cs, 64*cs+64).
// ============================================================
__global__ __launch_bounds__(128)
void k2_step2(const float* __restrict__ thetas,
              const float* __restrict__ evecs,
              const float* __restrict__ evals,
              float* __restrict__ out)
{
    __shared__ float  Vs[272];
    __shared__ float  cs[16], sn[16];
    __shared__ float4 g0s[256];

    const int t = threadIdx.x;
    const int batch = blockIdx.x >> 2;
    const int bc0 = (blockIdx.x & 3) * 64;

    stage_V(Vs, evecs, t);
    if (t < 16) {
        float s, c;
        sincosf(thetas[0] * evals[t], &s, &c);
        cs[t] = c;
        sn[t] = s;
    }
    __syncthreads();

    #pragma unroll
    for (int r = 0; r < 2; r++) {
        int e = t + r * 128;
        int k = e >> 4, kp = e & 15;
        g0s[kp * 16 + k] = gate_entry(Vs, cs, sn, k, kp);
    }
    __syncthreads();

    const int hh = t >> 2, q = t & 3;
    const int bc = bc0 + 2 * hh;             // fibers bc, bc+1

    const float4* src =
        g_inter4 + (batch * DIM + bc * 16) / 2;  // 16 float2 = 8 float4/fiber

    ull accA[2][4], accB[2][4];
    #pragma unroll
    for (int f = 0; f < 2; f++)
        #pragma unroll
        for (int j = 0; j < 4; j++) { accA[f][j] = 0ULL; accB[f][j] = 0ULL; }

    #pragma unroll
    for (int ch = 0; ch < 4; ch++) {
        float4 v0 = src[2 * ch];
        float4 v1 = src[2 * ch + 1];
        float4 w0 = src[8 + 2 * ch];
        float4 w1 = src[8 + 2 * ch + 1];
        ull xa[4] = { pack2(v0.x, v0.y), pack2(v0.z, v0.w),
                      pack2(v1.x, v1.y), pack2(v1.z, v1.w) };
        ull xb[4] = { pack2(w0.x, w0.y), pack2(w0.z, w0.w),
                      pack2(w1.x, w1.y), pack2(w1.z, w1.w) };
        #pragma unroll
        for (int cc = 0; cc < 4; cc++) {
            int kp = 4 * ch + cc;
            mac2(g0s + kp * 16 + q, xa[cc], xb[cc], accA, accB);
        }
    }

    float* outr = out + batch * DIM;
    float* outi = out + (size_t)BATCH * DIM + batch * DIM;
    #pragma unroll
    for (int f = 0; f < 2; f++)
        #pragma unroll
        for (int j = 0; j < 4; j++) {
            int k = q + 4 * j;
            float2 y = combine(accA[f][j], accB[f][j]);
            int d = k * 256 + bc + f;
            outr[d] = y.x;
            outi[d] = y.y;
        }
}

extern "C" void kernel_launch(void* const* d_in, const int* in_sizes, int n_in,
                              void* d_out, int out_size) {
    const float* thetas = (const float*)d_in[0];
    const float* evecs  = (const float*)d_in[1];
    const float* evals  = (const float*)d_in[2];
    const float* sreal  = (const float*)d_in[3];
    const float* simag  = (const float*)d_in[4];

    k1_steps01<<<BATCH * 4, 128>>>(thetas, evecs, evals, sreal, simag);
    k2_step2<<<BATCH * 4, 128>>>(thetas, evecs, evals, (float*)d_out);
}

// round 8
// speedup vs baseline: 1.3206x; 1.3206x over previous
#include <cuda_runtime.h>

#define BATCH 128
#define DIM   4096

typedef unsigned long long ull;

__device__ __forceinline__ ull pack2(float lo, float hi) {
    ull r;
    asm("mov.b64 %0, {%1, %2};" : "=l"(r) : "f"(lo), "f"(hi));
    return r;
}
__device__ __forceinline__ void unpack2(ull v, float& lo, float& hi) {
    asm("mov.b64 {%0, %1}, %2;" : "=f"(lo), "=f"(hi) : "l"(v));
}
__device__ __forceinline__ ull ffma2(ull a, ull b, ull c) {
    ull d;
    asm("fma.rn.f32x2 %0, %1, %2, %3;" : "=l"(d) : "l"(a), "l"(b), "l"(c));
    return d;
}

// padded smem: float4-aligned, spreads strided groups across banks
__device__ __forceinline__ int phys(int i) {
    return i + 2 * (i >> 4) + 2 * (i >> 8);
}
#define BUF_F2 4640

// Swap-free complex MAC:
//   accA += (Ur,Ur)*(xr,xi) ; accB += (Ui,Ui)*(xr,xi)
//   yr = accA.lo - accB.hi ; yi = accA.hi + accB.lo
// Gate G[kp*16+k] = float4(Ur,Ur,Ui,Ui), Ur=ar, Ui=-ai.

__device__ __forceinline__ void mac2(const float4* __restrict__ Gr,
                                     ull x0, ull x1,
                                     ull accA[2][4], ull accB[2][4]) {
    #pragma unroll
    for (int j = 0; j < 4; j++) {
        ulonglong2 g = *reinterpret_cast<const ulonglong2*>(Gr + 4 * j);
        accA[0][j] = ffma2(g.x, x0, accA[0][j]);
        accB[0][j] = ffma2(g.y, x0, accB[0][j]);
        accA[1][j] = ffma2(g.x, x1, accA[1][j]);
        accB[1][j] = ffma2(g.y, x1, accB[1][j]);
    }
}
__device__ __forceinline__ float2 combine(ull a, ull b) {
    float alo, ahi, blo, bhi;
    unpack2(a, alo, ahi);
    unpack2(b, blo, bhi);
    return make_float2(alo - bhi, ahi + blo);
}
__device__ __forceinline__ void zero_acc(ull accA[2][4], ull accB[2][4]) {
    #pragma unroll
    for (int f = 0; f < 2; f++)
        #pragma unroll
        for (int j = 0; j < 4; j++) { accA[f][j] = 0ULL; accB[f][j] = 0ULL; }
}

__global__ __launch_bounds__(512, 1)
void ulayer_kernel(const float* __restrict__ thetas,
                   const float* __restrict__ evecs,
                   const float* __restrict__ evals,
                   const float* __restrict__ sreal,
                   const float* __restrict__ simag,
                   float* __restrict__ out)
{
    extern __shared__ float2 smem[];
    float2* A  = smem;                   // step0 out: [a][k_c][b]
    float2* Bv = smem + BUF_F2;          // step1 out: [k_b][k_c][a]
    float4* g4 = reinterpret_cast<float4*>(smem + 2 * BUF_F2); // 3*256

    const int t = threadIdx.x;
    const int b0 = blockIdx.x;

    // scratch overlay inside A (dead before step0 writes A)
    float* Vs = reinterpret_cast<float*>(A);   // 16 rows, stride 17
    float* cs = reinterpret_cast<float*>(A) + 288;
    float* sn = reinterpret_cast<float*>(A) + 336;

    // ---- stage V and sincos ----
    if (t < 256) {
        Vs[(t >> 4) * 17 + (t & 15)] = evecs[t];
    }
    if (t >= 256 && t < 304) {
        int u = t - 256;
        int g = u >> 4, m = u & 15;
        float s, c;
        sincosf(thetas[g] * evals[m], &s, &c);
        cs[g * 16 + m] = c;
        sn[g * 16 + m] = s;
    }
    __syncthreads();

    // ---- build gates, layout G[kp*16+k] = (Ur,Ur,Ui,Ui) ----
    if (t < 256) {
        int k = t >> 4, kp = t & 15;
        #pragma unroll
        for (int g = 0; g < 3; g++) {
            float ar = 0.f, ai = 0.f;
            #pragma unroll
            for (int m = 0; m < 16; m++) {
                float p = Vs[k * 17 + m] * Vs[kp * 17 + m];
                ar += p * cs[g * 16 + m];
                ai += p * sn[g * 16 + m];
            }
            g4[g * 256 + kp * 16 + k] = make_float4(ar, ar, -ai, -ai);
        }
    }
    __syncthreads();

    const int h = t >> 2, q = t & 3;     // h in [0,128), q in [0,4)

    // ======== step 0: U2 contracts c; x direct from gmem ========
    // fibers fab = 2h, 2h+1 : a = h>>3, b = (2h)&15 (even)
    {
        const int a = h >> 3, bb = (2 * h) & 15;
        const float* xr = sreal + b0 * DIM + a * 256 + bb * 16;
        const float* xi = simag + b0 * DIM + a * 256 + bb * 16;
        const float4* G = g4 + 2 * 256;

        ull accA[2][4], accB[2][4];
        zero_acc(accA, accB);

        #pragma unroll
        for (int half = 0; half < 2; half++) {
            // load 8 c-values for both fibers (xr/xi), pack
            float4 r0a = *reinterpret_cast<const float4*>(xr + 8 * half);
            float4 r0b = *reinterpret_cast<const float4*>(xr + 8 * half + 4);
            float4 i0a = *reinterpret_cast<const float4*>(xi + 8 * half);
            float4 i0b = *reinterpret_cast<const float4*>(xi + 8 * half + 4);
            float4 r1a = *reinterpret_cast<const float4*>(xr + 16 + 8 * half);
            float4 r1b = *reinterpret_cast<const float4*>(xr + 16 + 8 * half + 4);
            float4 i1a = *reinterpret_cast<const float4*>(xi + 16 + 8 * half);
            float4 i1b = *reinterpret_cast<const float4*>(xi + 16 + 8 * half + 4);
            ull x0[8] = { pack2(r0a.x,i0a.x), pack2(r0a.y,i0a.y),
                          pack2(r0a.z,i0a.z), pack2(r0a.w,i0a.w),
                          pack2(r0b.x,i0b.x), pack2(r0b.y,i0b.y),
                          pack2(r0b.z,i0b.z), pack2(r0b.w,i0b.w) };
            ull x1[8] = { pack2(r1a.x,i1a.x), pack2(r1a.y,i1a.y),
                          pack2(r1a.z,i1a.z), pack2(r1a.w,i1a.w),
                          pack2(r1b.x,i1b.x), pack2(r1b.y,i1b.y),
                          pack2(r1b.z,i1b.z), pack2(r1b.w,i1b.w) };
            #pragma unroll
            for (int c = 0; c < 8; c++)
                mac2(G + (8 * half + c) * 16 + q, x0[c], x1[c], accA, accB);
        }
        // store y[a][k_c][b,b+1] as float4 (b even)
        #pragma unroll
        for (int j = 0; j < 4; j++) {
            int kc = q + 4 * j;
            float2 y0 = combine(accA[0][j], accB[0][j]);
            float2 y1 = combine(accA[1][j], accB[1][j]);
            int s = a * 256 + kc * 16 + bb;
            *reinterpret_cast<float4*>(A + phys(s)) =
                make_float4(y0.x, y0.y, y1.x, y1.y);
        }
    }
    __syncthreads();

    // ======== step 1: U1 contracts b; fibers contiguous in A ========
    // fibers f = 2h, 2h+1 over (a, k_c): a = h>>3, kc = (2h)&15 (even)
    {
        const int a = h >> 3, kc = (2 * h) & 15;
        const int p0 = phys(a * 256 + kc * 16);   // fiber0, 16 contig float2
        const int p1 = p0 + 18;                    // fiber1
        const float4* G = g4 + 1 * 256;

        ull accA[2][4], accB[2][4];
        zero_acc(accA, accB);

        #pragma unroll
        for (int half = 0; half < 2; half++) {
            float4 v0[4], v1[4];
            #pragma unroll
            for (int r = 0; r < 4; r++) {
                v0[r] = *reinterpret_cast<const float4*>(A + p0 + 8 * half + 2 * r);
                v1[r] = *reinterpret_cast<const float4*>(A + p1 + 8 * half + 2 * r);
            }
            #pragma unroll
            for (int r = 0; r < 4; r++) {
                ull x0a = *reinterpret_cast<ull*>(&v0[r]);
                ull x0b = *(reinterpret_cast<ull*>(&v0[r]) + 1);
                ull x1a = *reinterpret_cast<ull*>(&v1[r]);
                ull x1b = *(reinterpret_cast<ull*>(&v1[r]) + 1);
                mac2(G + (8 * half + 2 * r) * 16 + q, x0a, x1a, accA, accB);
                mac2(G + (8 * half + 2 * r + 1) * 16 + q, x0b, x1b, accA, accB);
            }
        }
        // store y[k_b][k_c][a] (and k_c+1)
        #pragma unroll
        for (int j = 0; j < 4; j++) {
            int kb = q + 4 * j;
            int s = kb * 256 + kc * 16 + a;
            Bv[phys(s)]      = combine(accA[0][j], accB[0][j]);
            Bv[phys(s + 16)] = combine(accA[1][j], accB[1][j]);
        }
    }
    __syncthreads();

    // ======== step 2: U0 contracts a; fibers contiguous in Bv ========
    // fibers f = 2h, 2h+1 over (k_b, k_c): kb = h>>3, kc = (2h)&15 (even)
    {
        const int kb = h >> 3, kc = (2 * h) & 15;
        const int p0 = phys(kb * 256 + kc * 16);
        const int p1 = p0 + 18;
        const float4* G = g4 + 0 * 256;

        ull accA[2][4], accB[2][4];
        zero_acc(accA, accB);

        #pragma unroll
        for (int half = 0; half < 2; half++) {
            float4 v0[4], v1[4];
            #pragma unroll
            for (int r = 0; r < 4; r++) {
                v0[r] = *reinterpret_cast<const float4*>(Bv + p0 + 8 * half + 2 * r);
                v1[r] = *reinterpret_cast<const float4*>(Bv + p1 + 8 * half + 2 * r);
            }
            #pragma unroll
            for (int r = 0; r < 4; r++) {
                ull x0a = *reinterpret_cast<ull*>(&v0[r]);
                ull x0b = *(reinterpret_cast<ull*>(&v0[r]) + 1);
                ull x1a = *reinterpret_cast<ull*>(&v1[r]);
                ull x1b = *(reinterpret_cast<ull*>(&v1[r]) + 1);
                mac2(G + (8 * half + 2 * r) * 16 + q, x0a, x1a, accA, accB);
                mac2(G + (8 * half + 2 * r + 1) * 16 + q, x0b, x1b, accA, accB);
            }
        }
        // write final output directly: d = k_a*256 + k_b*16 + k_c (kc even)
        float* outr = out + b0 * DIM;
        float* outi = out + (size_t)BATCH * DIM + b0 * DIM;
        #pragma unroll
        for (int j = 0; j < 4; j++) {
            int ka = q + 4 * j;
            float2 y0 = combine(accA[0][j], accB[0][j]);
            float2 y1 = combine(accA[1][j], accB[1][j]);
            int d = ka * 256 + kb * 16 + kc;
            *reinterpret_cast<float2*>(outr + d) = make_float2(y0.x, y1.x);
            *reinterpret_cast<float2*>(outi + d) = make_float2(y0.y, y1.y);
        }
    }
}

extern "C" void kernel_launch(void* const* d_in, const int* in_sizes, int n_in,
                              void* d_out, int out_size) {
    const float* thetas = (const float*)d_in[0];
    const float* evecs  = (const float*)d_in[1];
    const float* evals  = (const float*)d_in[2];
    const float* sreal  = (const float*)d_in[3];
    const float* simag  = (const float*)d_in[4];

    const int smem_bytes = 2 * BUF_F2 * sizeof(float2) + 3 * 256 * sizeof(float4);
    static bool attr_set = false;
    if (!attr_set) {
        cudaFuncSetAttribute(ulayer_kernel,
                             cudaFuncAttributeMaxDynamicSharedMemorySize,
                             smem_bytes);
        attr_set = true;
    }
    ulayer_kernel<<<BATCH, 512, smem_bytes>>>(thetas, evecs, evals,
                                              sreal, simag, (float*)d_out);
}

// round 9
// speedup vs baseline: 1.6054x; 1.2157x over previous
#include <cuda_runtime.h>

#define BATCH 128
#define DIM   4096

typedef unsigned long long ull;

__device__ __forceinline__ ull pack2(float lo, float hi) {
    ull r;
    asm("mov.b64 %0, {%1, %2};" : "=l"(r) : "f"(lo), "f"(hi));
    return r;
}
__device__ __forceinline__ void unpack2(ull v, float& lo, float& hi) {
    asm("mov.b64 {%0, %1}, %2;" : "=f"(lo), "=f"(hi) : "l"(v));
}
__device__ __forceinline__ ull ffma2(ull a, ull b, ull c) {
    ull d;
    asm("fma.rn.f32x2 %0, %1, %2, %3;" : "=l"(d) : "l"(a), "l"(b), "l"(c));
    return d;
}

// padded smem layout: float4-aligned, spreads strided fibers across banks
__device__ __forceinline__ int phys(int i) {
    return i + 2 * (i >> 4) + 2 * (i >> 8);
}
#define BUF_F2 4640

// Swap-free complex MAC:
//   accA += (Ur,Ur)*(xr,xi) ; accB += (Ui,Ui)*(xr,xi)
//   yr = accA.lo - accB.hi ; yi = accA.hi + accB.lo
// Gate G[kp*16+k] = float4(Ur,Ur,Ui,Ui), Ur=ar, Ui=-ai.

__device__ __forceinline__ float2 combine(ull a, ull b) {
    float alo, ahi, blo, bhi;
    unpack2(a, alo, ahi);
    unpack2(b, blo, bhi);
    return make_float2(alo - bhi, ahi + blo);
}
__device__ __forceinline__ void zero_acc(ull accA[4][4], ull accB[4][4]) {
    #pragma unroll
    for (int f = 0; f < 4; f++)
        #pragma unroll
        for (int j = 0; j < 4; j++) { accA[f][j] = 0ULL; accB[f][j] = 0ULL; }
}

// ---- step 0: contracted index has logical stride 1 ----
// Thread (h, q): fibers 4h..4h+3 (fiber phys stride 18), outputs k = q+4j.
// Gate rows for 8 kp are batch-preloaded into registers; inner loop is
// x-loads + independent FFMA2 only.
__device__ __forceinline__ void do_step0(const float2* __restrict__ IN,
                                         float2* __restrict__ OUT,
                                         const float4* __restrict__ G,
                                         int h, int q)
{
    const int pb0 = 72 * h + 2 * (h >> 2);
    const float4* Gq = G + q;

    ull accA[4][4], accB[4][4];
    zero_acc(accA, accB);

    #pragma unroll
    for (int half = 0; half < 2; half++) {
        // burst-preload gates for kp = 8*half .. 8*half+7 (32 LDS.128)
        ulonglong2 g[8][4];
        #pragma unroll
        for (int k8 = 0; k8 < 8; k8++)
            #pragma unroll
            for (int j = 0; j < 4; j++)
                g[k8][j] = *reinterpret_cast<const ulonglong2*>(
                    Gq + (8 * half + k8) * 16 + 4 * j);

        #pragma unroll
        for (int kp2 = 0; kp2 < 4; kp2++) {
            // one float4 per fiber covers kp = 8*half+2*kp2, +1
            float4 xv[4];
            #pragma unroll
            for (int f = 0; f < 4; f++)
                xv[f] = *reinterpret_cast<const float4*>(
                    IN + pb0 + 18 * f + 8 * half + 2 * kp2);
            #pragma unroll
            for (int sub = 0; sub < 2; sub++) {
                const int k8 = 2 * kp2 + sub;
                #pragma unroll
                for (int f = 0; f < 4; f++) {
                    ull xp = sub ? *(reinterpret_cast<ull*>(&xv[f]) + 1)
                                 : *reinterpret_cast<ull*>(&xv[f]);
                    #pragma unroll
                    for (int j = 0; j < 4; j++) {
                        accA[f][j] = ffma2(g[k8][j].x, xp, accA[f][j]);
                        accB[f][j] = ffma2(g[k8][j].y, xp, accB[f][j]);
                    }
                }
            }
        }
    }
    #pragma unroll
    for (int f = 0; f < 4; f++)
        #pragma unroll
        for (int j = 0; j < 4; j++)
            OUT[pb0 + 18 * f + (q + 4 * j)] = combine(accA[f][j], accB[f][j]);
}

// ---- steps 1 & 2: 4 fibers adjacent in phys (+1); PS = phys stride along kp
template<int PS>
__device__ __forceinline__ void do_step12(const float2* __restrict__ IN,
                                          float2* __restrict__ OUT,
                                          const float4* __restrict__ G,
                                          int pb, int q)
{
    const float4* Gq = G + q;

    ull accA[4][4], accB[4][4];
    zero_acc(accA, accB);

    #pragma unroll
    for (int half = 0; half < 2; half++) {
        ulonglong2 g[8][4];
        #pragma unroll
        for (int k8 = 0; k8 < 8; k8++)
            #pragma unroll
            for (int j = 0; j < 4; j++)
                g[k8][j] = *reinterpret_cast<const ulonglong2*>(
                    Gq + (8 * half + k8) * 16 + 4 * j);

        #pragma unroll
        for (int k8 = 0; k8 < 8; k8++) {
            const int kp = 8 * half + k8;
            float4 v01 = *reinterpret_cast<const float4*>(IN + pb + kp * PS);
            float4 v23 = *reinterpret_cast<const float4*>(IN + pb + 2 + kp * PS);
            ull xp[4];
            xp[0] = *reinterpret_cast<ull*>(&v01);
            xp[1] = *(reinterpret_cast<ull*>(&v01) + 1);
            xp[2] = *reinterpret_cast<ull*>(&v23);
            xp[3] = *(reinterpret_cast<ull*>(&v23) + 1);
            #pragma unroll
            for (int f = 0; f < 4; f++)
                #pragma unroll
                for (int j = 0; j < 4; j++) {
                    accA[f][j] = ffma2(g[k8][j].x, xp[f], accA[f][j]);
                    accB[f][j] = ffma2(g[k8][j].y, xp[f], accB[f][j]);
                }
        }
    }
    // stores: fibers f,f+1 adjacent -> float4 store per (j, pair)
    #pragma unroll
    for (int j = 0; j < 4; j++) {
        int k = q + 4 * j;
        float2 y0 = combine(accA[0][j], accB[0][j]);
        float2 y1 = combine(accA[1][j], accB[1][j]);
        *reinterpret_cast<float4*>(OUT + pb + k * PS) =
            make_float4(y0.x, y0.y, y1.x, y1.y);
        y0 = combine(accA[2][j], accB[2][j]);
        y1 = combine(accA[3][j], accB[3][j]);
        *reinterpret_cast<float4*>(OUT + pb + 2 + k * PS) =
            make_float4(y0.x, y0.y, y1.x, y1.y);
    }
}

__global__ __launch_bounds__(256, 1)
void ulayer_kernel(const float* __restrict__ thetas,
                   const float* __restrict__ evecs,
                   const float* __restrict__ evals,
                   const float* __restrict__ sreal,
                   const float* __restrict__ simag,
                   float* __restrict__ out)
{
    extern __shared__ float2 smem[];
    float2* A  = smem;                  // BUF_F2 float2
    float2* Bv = smem + BUF_F2;         // BUF_F2 float2
    float4* g4 = reinterpret_cast<float4*>(smem + 2 * BUF_F2); // 3*256 float4

    const int t = threadIdx.x;
    const int b = blockIdx.x;

    // scratch overlay inside B (dead until step 0 writes B, after syncs)
    float* Vs = reinterpret_cast<float*>(Bv);   // 16 rows, stride 17
    float* cs = reinterpret_cast<float*>(Bv) + 288;
    float* sn = reinterpret_cast<float*>(Bv) + 336;

    // ---- stage V and sincos ----
    {
        int j = t >> 4, m = t & 15;
        Vs[j * 17 + m] = evecs[t];               // V[j][m]
    }
    if (t < 48) {
        int g = t >> 4, m = t & 15;
        float s, c;
        sincosf(thetas[g] * evals[m], &s, &c);
        cs[g * 16 + m] = c;
        sn[g * 16 + m] = s;
    }
    __syncthreads();

    // ---- build gates, layout G[kp*16 + k] = (Ur, Ur, Ui, Ui) ----
    {
        int k = t >> 4, kp = t & 15;
        #pragma unroll
        for (int g = 0; g < 3; g++) {
            float ar = 0.f, ai = 0.f;
            #pragma unroll
            for (int m = 0; m < 16; m++) {
                float p = Vs[k * 17 + m] * Vs[kp * 17 + m];
                ar += p * cs[g * 16 + m];
                ai += p * sn[g * 16 + m];
            }
            // Ur = ar, Ui = -ai
            g4[g * 256 + kp * 16 + k] = make_float4(ar, ar, -ai, -ai);
        }
    }

    // ---- load state into A (concurrent with gate build) ----
    const float* srg = sreal + b * DIM;
    const float* sig = simag + b * DIM;
    #pragma unroll
    for (int w = 0; w < 16; w++) {
        int i = t + w * 256;
        A[phys(i)] = make_float2(srg[i], sig[i]);
    }
    __syncthreads();

    const int h = t >> 2, q = t & 3;   // h in [0,64), q in [0,4)

    // step 0: U2 on stride-1 index, fibers 4h..4h+3
    do_step0(A, Bv, g4 + 2 * 256, h, q);
    __syncthreads();

    // step 1: U1 on stride-16 index; fibers f0=4h..4h+3
    {
        int f0 = 4 * h;
        int pb = (f0 >> 4) * 290 + (f0 & 15);
        do_step12<18>(Bv, A, g4 + 1 * 256, pb, q);
    }
    __syncthreads();

    // step 2: U0 on stride-256 index; fibers f0=4h..4h+3
    {
        int f0 = 4 * h;
        int pb = f0 + 2 * (f0 >> 4);
        do_step12<290>(A, Bv, g4 + 0 * 256, pb, q);
    }
    __syncthreads();

    // ---- write output [2, BATCH, DIM] from B ----
    float* outr = out + b * DIM;
    float* outi = out + (size_t)BATCH * DIM + b * DIM;
    #pragma unroll
    for (int w = 0; w < 16; w++) {
        int i = t + w * 256;
        float2 v = Bv[phys(i)];
        outr[i] = v.x;
        outi[i] = v.y;
    }
}

extern "C" void kernel_launch(void* const* d_in, const int* in_sizes, int n_in,
                              void* d_out, int out_size) {
    const float* thetas = (const float*)d_in[0];
    const float* evecs  = (const float*)d_in[1];
    const float* evals  = (const float*)d_in[2];
    const float* sreal  = (const float*)d_in[3];
    const float* simag  = (const float*)d_in[4];

    const int smem_bytes = 2 * BUF_F2 * sizeof(float2) + 3 * 256 * sizeof(float4);
    static bool attr_set = false;
    if (!attr_set) {
        cudaFuncSetAttribute(ulayer_kernel,
                             cudaFuncAttributeMaxDynamicSharedMemorySize,
                             smem_bytes);
        attr_set = true;
    }
    ulayer_kernel<<<BATCH, 256, smem_bytes>>>(thetas, evecs, evals,
                                              sreal, simag, (float*)d_out);
}